// round 3
// baseline (speedup 1.0000x reference)
#include <cuda_runtime.h>

#define Dn 4
#define Cn 64
#define Hn 64
#define Wn 64
#define Nn 4096
#define QKn 32

// ------------------ static device scratch (no runtime allocation) ------------------
__device__ __align__(16) float g_qt[Dn * Nn * QKn];     // q transposed: [d][n][32]
__device__ __align__(16) float g_k [Dn * QKn * Nn];     // k: [d][c][m]
__device__ __align__(16) float g_s [Dn * Nn * Nn];      // raw scores [d][n][m] (256MB)
__device__ float g_mx [Dn * Nn];                        // softmax1 row max
__device__ float g_sum[Dn * Nn];                        // softmax1 row sum

// ------------------ packed f32x2 helpers (Blackwell) ------------------
__device__ __forceinline__ unsigned long long pk2(float a, float b) {
    unsigned long long r;
    asm("mov.b64 %0, {%1,%2};" : "=l"(r) : "f"(a), "f"(b));
    return r;
}
__device__ __forceinline__ float2 upk2(unsigned long long v) {
    float a, b;
    asm("mov.b64 {%0,%1}, %2;" : "=f"(a), "=f"(b) : "l"(v));
    return make_float2(a, b);
}
#define FMA2(d, a, b) asm("fma.rn.f32x2 %0, %1, %2, %0;" : "+l"(d) : "l"(a), "l"(b))
#define MUL2(d, a, b) asm("mul.rn.f32x2 %0, %1, %2;" : "=l"(d) : "l"(a), "l"(b))

// ============================================================================
// K1: 3x3 SAME conv for q and k. grid (H, D, 2proj), 256 thr = 32 oc x 8 wgrp.
// Each thread computes 8 outputs along w for one output channel.
// ============================================================================
__global__ __launch_bounds__(256) void conv_qk(
    const float* __restrict__ x,
    const float* __restrict__ qw, const float* __restrict__ qb,
    const float* __restrict__ kw, const float* __restrict__ kb)
{
    __shared__ float xs[3][16][66];    // (dy, ic_local, w+1), zero side pads
    __shared__ float wsm[16][9][32];   // (ic_local, tap, oc)

    const int h = blockIdx.x, d = blockIdx.y, proj = blockIdx.z;
    const int tid = threadIdx.x;
    const int oc = tid & 31, wg = tid >> 5;

    const float* wsrc = proj ? kw : qw;
    float acc[8];
    {
        float b = proj ? kb[oc] : qb[oc];
#pragma unroll
        for (int j = 0; j < 8; j++) acc[j] = b;
    }

    for (int chunk = 0; chunk < 4; chunk++) {
        for (int i = tid; i < 16 * 64; i += 256) {
            int icl = i >> 6, w = i & 63;
            const float* xp = x + ((size_t)(d * Cn + chunk * 16 + icl)) * (size_t)(Hn * Wn);
#pragma unroll
            for (int dy = 0; dy < 3; dy++) {
                int hh = h + dy - 1;
                xs[dy][icl][w + 1] = (hh >= 0 && hh < Hn) ? xp[hh * Wn + w] : 0.f;
            }
            if (w == 0) {
#pragma unroll
                for (int dy = 0; dy < 3; dy++) { xs[dy][icl][0] = 0.f; xs[dy][icl][65] = 0.f; }
            }
        }
        for (int i = tid; i < 16 * 9 * 32; i += 256) {
            int icl = i / 288, rem = i % 288, tap = rem >> 5, o = rem & 31;
            wsm[icl][tap][o] = wsrc[(o * Cn + chunk * 16 + icl) * 9 + tap];
        }
        __syncthreads();

        for (int icl = 0; icl < 16; icl++) {
#pragma unroll
            for (int dy = 0; dy < 3; dy++) {
                float xv[10];
#pragma unroll
                for (int t = 0; t < 10; t++) xv[t] = xs[dy][icl][wg * 8 + t];
#pragma unroll
                for (int dx = 0; dx < 3; dx++) {
                    float wv = wsm[icl][dy * 3 + dx][oc];
#pragma unroll
                    for (int j = 0; j < 8; j++) acc[j] = fmaf(wv, xv[dx + j], acc[j]);
                }
            }
        }
        __syncthreads();
    }

    const int n = h * Wn + wg * 8;
    if (proj == 0) {
#pragma unroll
        for (int j = 0; j < 8; j++)
            g_qt[((size_t)(d * Nn + n + j)) * QKn + oc] = acc[j];
    } else {
#pragma unroll
        for (int j = 0; j < 8; j++)
            g_k[((size_t)(d * QKn + oc)) * Nn + n + j] = acc[j];
    }
}

// ============================================================================
// K2: scores s[d,n,m] = sum_c q[n,c] k[c,m]; write raw scores; online softmax1
// row stats. grid (N/32, D), 256 thr. warp w owns rows 4w..4w+3; lane owns
// m-quad lane*4 within a 128-m tile. f32x2 inner product.
// ============================================================================
__global__ __launch_bounds__(256) void qk_scores()
{
    __shared__ float qs2[32][64];      // [r][2c+{0,1}] q duplicated pairs
    __shared__ float4 ks[32][32];      // [c][m_quad]

    const int d = blockIdx.y, n0 = blockIdx.x * 32;
    const int tid = threadIdx.x, lane = tid & 31, warp = tid >> 5;

    {
        const float* qsrc = g_qt + ((size_t)(d * Nn + n0)) * QKn;
        float4 qv = ((const float4*)qsrc)[tid];     // 32 rows x 8 quads
        int r = tid >> 3, cb = (tid & 7) * 4;
        qs2[r][(cb + 0) * 2] = qv.x; qs2[r][(cb + 0) * 2 + 1] = qv.x;
        qs2[r][(cb + 1) * 2] = qv.y; qs2[r][(cb + 1) * 2 + 1] = qv.y;
        qs2[r][(cb + 2) * 2] = qv.z; qs2[r][(cb + 2) * 2 + 1] = qv.z;
        qs2[r][(cb + 3) * 2] = qv.w; qs2[r][(cb + 3) * 2 + 1] = qv.w;
    }

    float mx[4], sm[4];
#pragma unroll
    for (int i = 0; i < 4; i++) { mx[i] = -1e30f; sm[i] = 0.f; }
    const int r0 = warp * 4;

    for (int mt = 0; mt < Nn / 128; mt++) {
        const int m0 = mt * 128;
        __syncthreads();
        for (int i = tid; i < 1024; i += 256) {
            int c = i >> 5, mq = i & 31;
            ks[c][mq] = *(const float4*)(g_k + ((size_t)(d * QKn + c)) * Nn + m0 + mq * 4);
        }
        __syncthreads();

        unsigned long long a0[4], a1[4];
#pragma unroll
        for (int i = 0; i < 4; i++) { a0[i] = 0ull; a1[i] = 0ull; }

#pragma unroll
        for (int c = 0; c < 32; c++) {
            ulonglong2 kv = *(const ulonglong2*)&ks[c][lane];
#pragma unroll
            for (int i = 0; i < 4; i++) {
                unsigned long long qp = *(const unsigned long long*)&qs2[r0 + i][c * 2];
                FMA2(a0[i], qp, kv.x);
                FMA2(a1[i], qp, kv.y);
            }
        }

#pragma unroll
        for (int i = 0; i < 4; i++) {
            float2 p0 = upk2(a0[i]), p1 = upk2(a1[i]);
            *(float4*)(g_s + ((size_t)(d * Nn + n0 + r0 + i)) * Nn + m0 + lane * 4)
                = make_float4(p0.x, p0.y, p1.x, p1.y);
            float tm = fmaxf(fmaxf(p0.x, p0.y), fmaxf(p1.x, p1.y));
#pragma unroll
            for (int o = 16; o > 0; o >>= 1)
                tm = fmaxf(tm, __shfl_xor_sync(0xffffffffu, tm, o));
            float nm = fmaxf(mx[i], tm);
            float es = __expf(p0.x - nm) + __expf(p0.y - nm)
                     + __expf(p1.x - nm) + __expf(p1.y - nm);
#pragma unroll
            for (int o = 16; o > 0; o >>= 1)
                es += __shfl_xor_sync(0xffffffffu, es, o);
            sm[i] = sm[i] * __expf(mx[i] - nm) + es;
            mx[i] = nm;
        }
    }

    if (lane == 0) {
#pragma unroll
        for (int i = 0; i < 4; i++) {
            g_mx [d * Nn + n0 + r0 + i] = mx[i];
            g_sum[d * Nn + n0 + r0 + i] = sm[i];
        }
    }
}

// ============================================================================
// K3: t = softmax1(s) + atten; online softmax2; out = gamma*(P @ V^T)/sum + x.
// grid (N/32, D), 256 thr. 64-m tiles. GEMM thread = 2 n-rows x 4 c-chans.
// ============================================================================
__global__ __launch_bounds__(256) void attn_v(
    const float* __restrict__ x, const float* __restrict__ atten,
    const float* __restrict__ gamma, float* __restrict__ out)
{
    __shared__ float ts[64 * 34];      // t / e transposed: [m][n], pad 34
    __shared__ float vs[64 * 68];      // v tile: [m][c], pad 68
    __shared__ float mx1[32], is1[32], m2s[32], sum2s[32], scls[32];

    const int d = blockIdx.y;
    const int gn0 = blockIdx.x * 32;
    const int tid = threadIdx.x;
    const int lane = tid & 31, warp = tid >> 5;

    if (tid < 32) {
        mx1[tid] = g_mx[d * Nn + gn0 + tid];
        is1[tid] = 1.0f / g_sum[d * Nn + gn0 + tid];
        m2s[tid] = -1e30f;
        sum2s[tid] = 0.f;
    }

    const int cq = tid & 15, np = tid >> 4;
    const int c0 = cq * 4, n0 = np * 2;
    unsigned long long acc00 = 0, acc01 = 0, acc10 = 0, acc11 = 0;

    const int an = tid >> 4;       // phase A: rows an, an+16
    const int amq = tid & 15;      // m-quad

    for (int m0 = 0; m0 < Nn; m0 += 64) {
        __syncthreads();   // previous GEMM done before overwriting ts/vs

        // --- phase A: t tile -> ts[m][n] (transposed) ---
#pragma unroll
        for (int kk = 0; kk < 2; kk++) {
            int n = an + 16 * kk;
            size_t base = ((size_t)(d * Nn + gn0 + n)) * Nn + m0 + amq * 4;
            float4 s4 = *(const float4*)(g_s + base);
            float4 a4 = *(const float4*)(atten + base);
            float mr = mx1[n], ir = is1[n];
            ts[(amq * 4 + 0) * 34 + n] = __expf(s4.x - mr) * ir + a4.x;
            ts[(amq * 4 + 1) * 34 + n] = __expf(s4.y - mr) * ir + a4.y;
            ts[(amq * 4 + 2) * 34 + n] = __expf(s4.z - mr) * ir + a4.z;
            ts[(amq * 4 + 3) * 34 + n] = __expf(s4.w - mr) * ir + a4.w;
        }
        // --- v tile -> vs[m][c] (transposed) ---
#pragma unroll
        for (int k = 0; k < 4; k++) {
            int i = tid + 256 * k;
            int cv = i >> 6;           // c-quad 0..15
            int m = i & 63;
            const float* xp = x + ((size_t)(d * Cn + cv * 4)) * Nn + m0 + m;
            float4 v;
            v.x = xp[0]; v.y = xp[Nn]; v.z = xp[2 * Nn]; v.w = xp[3 * Nn];
            *(float4*)&vs[m * 68 + cv * 4] = v;
        }
        __syncthreads();

        // --- phase B: online softmax2, warp w owns rows 4w..4w+3 ---
        {
            float t0[4], t1[4], tm[4];
#pragma unroll
            for (int i = 0; i < 4; i++) {
                int r = warp * 4 + i;
                t0[i] = ts[lane * 34 + r];
                t1[i] = ts[(lane + 32) * 34 + r];
                tm[i] = fmaxf(t0[i], t1[i]);
            }
#pragma unroll
            for (int o = 16; o > 0; o >>= 1) {
#pragma unroll
                for (int i = 0; i < 4; i++)
                    tm[i] = fmaxf(tm[i], __shfl_xor_sync(0xffffffffu, tm[i], o));
            }
            float es[4], nm[4], sc[4];
#pragma unroll
            for (int i = 0; i < 4; i++) {
                int r = warp * 4 + i;
                nm[i] = fmaxf(m2s[r], tm[i]);
                sc[i] = __expf(m2s[r] - nm[i]);
                float e0 = __expf(t0[i] - nm[i]);
                float e1 = __expf(t1[i] - nm[i]);
                ts[lane * 34 + r] = e0;
                ts[(lane + 32) * 34 + r] = e1;
                es[i] = e0 + e1;
            }
#pragma unroll
            for (int o = 16; o > 0; o >>= 1) {
#pragma unroll
                for (int i = 0; i < 4; i++)
                    es[i] += __shfl_xor_sync(0xffffffffu, es[i], o);
            }
            if (lane == 0) {
#pragma unroll
                for (int i = 0; i < 4; i++) {
                    int r = warp * 4 + i;
                    sum2s[r] = sum2s[r] * sc[i] + es[i];
                    m2s[r] = nm[i];
                    scls[r] = sc[i];
                }
            }
        }
        __syncthreads();

        // --- phase C: rescale accumulators, f32x2 GEMM over this m tile ---
        {
            float sa = scls[n0], sb = scls[n0 + 1];
            unsigned long long s2a = pk2(sa, sa), s2b = pk2(sb, sb);
            MUL2(acc00, acc00, s2a); MUL2(acc01, acc01, s2a);
            MUL2(acc10, acc10, s2b); MUL2(acc11, acc11, s2b);
#pragma unroll 8
            for (int m = 0; m < 64; m++) {
                float2 e2 = *(const float2*)&ts[m * 34 + n0];
                ulonglong2 v2 = *(const ulonglong2*)&vs[m * 68 + c0];
                unsigned long long ex = pk2(e2.x, e2.x);
                unsigned long long ey = pk2(e2.y, e2.y);
                FMA2(acc00, v2.x, ex); FMA2(acc01, v2.y, ex);
                FMA2(acc10, v2.x, ey); FMA2(acc11, v2.y, ey);
            }
        }
    }

    // --- epilogue: out = gamma * acc / sum2 + x ---
    {
        float g = gamma[0];
        float inv0 = 1.0f / sum2s[n0];
        float inv1 = 1.0f / sum2s[n0 + 1];
        float2 p00 = upk2(acc00), p01 = upk2(acc01);
        float2 p10 = upk2(acc10), p11 = upk2(acc11);
        float r0v[4] = {p00.x, p00.y, p01.x, p01.y};
        float r1v[4] = {p10.x, p10.y, p11.x, p11.y};
#pragma unroll
        for (int cc = 0; cc < 4; cc++) {
            size_t i0 = ((size_t)(d * Cn + c0 + cc)) * Nn + gn0 + n0;
            out[i0]     = g * r0v[cc] * inv0 + x[i0];
            out[i0 + 1] = g * r1v[cc] * inv1 + x[i0 + 1];
        }
    }
}

// ============================================================================
extern "C" void kernel_launch(void* const* d_in, const int* in_sizes, int n_in,
                              void* d_out, int out_size)
{
    const float* x   = (const float*)d_in[0];
    const float* att = (const float*)d_in[1];
    const float* qw  = (const float*)d_in[2];
    const float* qb  = (const float*)d_in[3];
    const float* kw  = (const float*)d_in[4];
    const float* kb  = (const float*)d_in[5];
    const float* gm  = (const float*)d_in[6];
    float* out = (float*)d_out;

    conv_qk  <<<dim3(Hn, Dn, 2), 256>>>(x, qw, qb, kw, kb);
    qk_scores<<<dim3(Nn / 32, Dn), 256>>>();
    attn_v   <<<dim3(Nn / 32, Dn), 256>>>(x, att, gm, out);
}

// round 4
// speedup vs baseline: 1.1452x; 1.1452x over previous
#include <cuda_runtime.h>

#define Dn 4
#define Cn 64
#define Hn 64
#define Wn 64
#define Nn 4096
#define QKn 32
#define B1 20.0f
#define B2 8.0f

typedef unsigned long long u64;

__device__ __align__(16) float g_qt[Dn * Nn * QKn];         // q: [d][n][32]
__device__ __align__(16) float g_k [Dn * QKn * Nn];         // k: [d][c][m]
__device__ __align__(16) float g_vt[(size_t)Dn * Nn * Cn];  // v^T: [d][m][c]
__device__ __align__(16) float g_s [(size_t)Dn * Nn * Nn];  // raw scores [d][n][m]
__device__ float g_sum[Dn * Nn];                            // softmax1 sums

__device__ __forceinline__ float2 upk2(u64 v) {
    float a, b;
    asm("mov.b64 {%0,%1}, %2;" : "=f"(a), "=f"(b) : "l"(v));
    return make_float2(a, b);
}
#define FMA2(d, a, b) asm("fma.rn.f32x2 %0, %1, %2, %0;" : "+l"(d) : "l"(a), "l"(b))

// ========================= K1: conv3x3 for q,k =========================
__global__ __launch_bounds__(256) void conv_qk(
    const float* __restrict__ x,
    const float* __restrict__ qw, const float* __restrict__ qb,
    const float* __restrict__ kw, const float* __restrict__ kb)
{
    __shared__ float xs[3][16][66];
    __shared__ float wsm[16][9][32];
    const int h = blockIdx.x, d = blockIdx.y, proj = blockIdx.z;
    const int tid = threadIdx.x, oc = tid & 31, wg = tid >> 5;
    const float* wsrc = proj ? kw : qw;
    float acc[8];
    float bia = proj ? kb[oc] : qb[oc];
#pragma unroll
    for (int j = 0; j < 8; j++) acc[j] = bia;

    for (int chunk = 0; chunk < 4; chunk++) {
        for (int i = tid; i < 16 * 64; i += 256) {
            int icl = i >> 6, w = i & 63;
            const float* xp = x + ((size_t)(d * Cn + chunk * 16 + icl)) * (Hn * Wn);
#pragma unroll
            for (int dy = 0; dy < 3; dy++) {
                int hh = h + dy - 1;
                xs[dy][icl][w + 1] = (hh >= 0 && hh < Hn) ? xp[hh * Wn + w] : 0.f;
            }
            if (w == 0)
#pragma unroll
                for (int dy = 0; dy < 3; dy++) { xs[dy][icl][0] = 0.f; xs[dy][icl][65] = 0.f; }
        }
        for (int i = tid; i < 16 * 9 * 32; i += 256) {
            int icl = i / 288, rem = i % 288;
            wsm[icl][rem >> 5][rem & 31] = wsrc[((rem & 31) * Cn + chunk * 16 + icl) * 9 + (rem >> 5)];
        }
        __syncthreads();
        for (int icl = 0; icl < 16; icl++) {
#pragma unroll
            for (int dy = 0; dy < 3; dy++) {
                float xv[10];
#pragma unroll
                for (int t = 0; t < 10; t++) xv[t] = xs[dy][icl][wg * 8 + t];
#pragma unroll
                for (int dx = 0; dx < 3; dx++) {
                    float wv = wsm[icl][dy * 3 + dx][oc];
#pragma unroll
                    for (int j = 0; j < 8; j++) acc[j] = fmaf(wv, xv[dx + j], acc[j]);
                }
            }
        }
        __syncthreads();
    }
    const int n = h * Wn + wg * 8;
    if (proj == 0) {
#pragma unroll
        for (int j = 0; j < 8; j++) g_qt[((size_t)(d * Nn + n + j)) * QKn + oc] = acc[j];
    } else {
#pragma unroll
        for (int j = 0; j < 8; j++) g_k[((size_t)(d * QKn + oc)) * Nn + n + j] = acc[j];
    }
}

// ========================= K1.5: v transpose =========================
__global__ __launch_bounds__(256) void transpose_v(const float* __restrict__ x)
{
    __shared__ float t[32][33];
    const int m0 = blockIdx.x * 32, c0 = blockIdx.y * 32, d = blockIdx.z;
    const int i = threadIdx.x & 31, j = threadIdx.x >> 5;
#pragma unroll
    for (int r = 0; r < 32; r += 8)
        t[j + r][i] = x[((size_t)(d * Cn + c0 + j + r)) * Nn + m0 + i];
    __syncthreads();
#pragma unroll
    for (int r = 0; r < 32; r += 8)
        g_vt[((size_t)(d * Nn + m0 + j + r)) * Cn + c0 + i] = t[i][j + r];
}

// ========================= K2: scores + softmax1 sums =========================
// grid (Nn/64, Dn), 256 thr. block 64n x 128m-tile, thread 4n x 8m.
__global__ __launch_bounds__(256) void qk_scores()
{
    __shared__ float qs[32 * 132];   // [c][2n dup], stride 132
    __shared__ float ks[32 * 140];   // [c][m swizzled: col+4*(col>>5)], stride 140

    const int d = blockIdx.y, gn0 = blockIdx.x * 64;
    const int tid = threadIdx.x;
    const int mg = tid & 15, ng = tid >> 4;
    const int kcol = 8 * mg + 4 * (mg >> 2);

    // fill q duplicated (once)
#pragma unroll
    for (int k = 0; k < 2; k++) {
        int i = tid + 256 * k;
        int n = i >> 3, cq = i & 7;
        float4 q4 = *(const float4*)(g_qt + ((size_t)(d * Nn + gn0 + n)) * QKn + cq * 4);
        float v[4] = {q4.x, q4.y, q4.z, q4.w};
#pragma unroll
        for (int e = 0; e < 4; e++)
            *(float2*)&qs[(cq * 4 + e) * 132 + 2 * n] = make_float2(v[e], v[e]);
    }

    float part[4] = {0.f, 0.f, 0.f, 0.f};

    for (int m0 = 0; m0 < Nn; m0 += 128) {
        __syncthreads();
#pragma unroll
        for (int k = 0; k < 4; k++) {
            int i = tid + 256 * k;
            int c = i >> 5, mq = i & 31;
            *(float4*)&ks[c * 140 + 4 * mq + 4 * (mq >> 3)] =
                *(const float4*)(g_k + ((size_t)(d * QKn + c)) * Nn + m0 + 4 * mq);
        }
        __syncthreads();

        u64 acc[4][4];
#pragma unroll
        for (int i = 0; i < 4; i++)
#pragma unroll
            for (int p = 0; p < 4; p++) acc[i][p] = 0ull;

#pragma unroll 8
        for (int c = 0; c < QKn; c++) {
            ulonglong2 qA = *(const ulonglong2*)&qs[c * 132 + 8 * ng];
            ulonglong2 qB = *(const ulonglong2*)&qs[c * 132 + 8 * ng + 4];
            ulonglong2 kA = *(const ulonglong2*)&ks[c * 140 + kcol];
            ulonglong2 kB = *(const ulonglong2*)&ks[c * 140 + kcol + 4];
            u64 q[4]  = {qA.x, qA.y, qB.x, qB.y};
            u64 kk[4] = {kA.x, kA.y, kB.x, kB.y};
#pragma unroll
            for (int i = 0; i < 4; i++) {
                FMA2(acc[i][0], q[i], kk[0]);
                FMA2(acc[i][1], q[i], kk[1]);
                FMA2(acc[i][2], q[i], kk[2]);
                FMA2(acc[i][3], q[i], kk[3]);
            }
        }

#pragma unroll
        for (int i = 0; i < 4; i++) {
            float2 p0 = upk2(acc[i][0]), p1 = upk2(acc[i][1]);
            float2 p2 = upk2(acc[i][2]), p3 = upk2(acc[i][3]);
            size_t base = ((size_t)(d * Nn + gn0 + 4 * ng + i)) * Nn + m0 + 8 * mg;
            *(float4*)(g_s + base)     = make_float4(p0.x, p0.y, p1.x, p1.y);
            *(float4*)(g_s + base + 4) = make_float4(p2.x, p2.y, p3.x, p3.y);
            part[i] += __expf(p0.x - B1) + __expf(p0.y - B1)
                     + __expf(p1.x - B1) + __expf(p1.y - B1)
                     + __expf(p2.x - B1) + __expf(p2.y - B1)
                     + __expf(p3.x - B1) + __expf(p3.y - B1);
        }
    }

#pragma unroll
    for (int o = 1; o < 16; o <<= 1)
#pragma unroll
        for (int i = 0; i < 4; i++)
            part[i] += __shfl_xor_sync(0xffffffffu, part[i], o);
    if (mg == 0)
#pragma unroll
        for (int i = 0; i < 4; i++)
            g_sum[d * Nn + gn0 + 4 * ng + i] = part[i];
}

// ========================= K3: double-softmax attn @ V + residual =========================
// grid (Nn/64, Dn), 256 thr, dynamic smem. block 64n x 64c, m-tiles 64, thread 4n x 4c.
__global__ __launch_bounds__(256) void attn_v(
    const float* __restrict__ x, const float* __restrict__ atten,
    const float* __restrict__ gamma, float* __restrict__ out)
{
    extern __shared__ float sh[];
    float* ts  = sh;                       // [64][132] e duplicated: [m][2n]
    float* vs  = sh + 64 * 132;            // [64][68]  v: [m][c]
    float* is1 = sh + 64 * 132 + 64 * 68;  // [64]
    float* s2  = is1 + 64;                 // [64]

    const int d = blockIdx.y, gn0 = blockIdx.x * 64;
    const int tid = threadIdx.x, lane = tid & 31, w = tid >> 5;
    const int cg = tid & 15, ng = tid >> 4;
    const int a = lane & 7, b = lane >> 3;

    if (tid < 64) is1[tid] = 1.0f / g_sum[d * Nn + gn0 + tid];

    u64 acc[4][2];
#pragma unroll
    for (int i = 0; i < 4; i++) { acc[i][0] = 0ull; acc[i][1] = 0ull; }
    float part[2] = {0.f, 0.f};

    for (int m0 = 0; m0 < Nn; m0 += 64) {
        __syncthreads();
        // phase A: e = exp(exp(s-B1)/sum1 + atten - B2), stored dup-transposed
#pragma unroll
        for (int p = 0; p < 4; p++) {
#pragma unroll
            for (int q = 0; q < 2; q++) {
                int n = 32 * q + 4 * w + b;
                int ml = 16 * p + 2 * a;
                size_t base = ((size_t)(d * Nn + gn0 + n)) * Nn + m0 + ml;
                float2 sv = *(const float2*)(g_s + base);
                float2 av = *(const float2*)(atten + base);
                float ir = is1[n];
                float e0 = __expf(fmaf(__expf(sv.x - B1), ir, av.x) - B2);
                float e1 = __expf(fmaf(__expf(sv.y - B1), ir, av.y) - B2);
                part[q] += e0 + e1;
                *(float2*)&ts[ml * 132 + 2 * n]       = make_float2(e0, e0);
                *(float2*)&ts[(ml + 1) * 132 + 2 * n] = make_float2(e1, e1);
            }
        }
        // v tile (pre-transposed source)
#pragma unroll
        for (int k = 0; k < 4; k++) {
            int m = (tid >> 4) + 16 * k;
            *(float4*)&vs[m * 68 + 4 * cg] =
                *(const float4*)(g_vt + ((size_t)(d * Nn + m0 + m)) * Cn + 4 * cg);
        }
        __syncthreads();

        // GEMM: acc[n][c-pairs] += e * v
#pragma unroll 8
        for (int m = 0; m < 64; m++) {
            ulonglong2 eA = *(const ulonglong2*)&ts[m * 132 + 8 * ng];
            ulonglong2 vv = *(const ulonglong2*)&vs[m * 68 + 4 * cg];
            FMA2(acc[0][0], eA.x, vv.x); FMA2(acc[0][1], eA.x, vv.y);
            FMA2(acc[1][0], eA.y, vv.x); FMA2(acc[1][1], eA.y, vv.y);
            ulonglong2 eB = *(const ulonglong2*)&ts[m * 132 + 8 * ng + 4];
            FMA2(acc[2][0], eB.x, vv.x); FMA2(acc[2][1], eB.x, vv.y);
            FMA2(acc[3][0], eB.y, vv.x); FMA2(acc[3][1], eB.y, vv.y);
        }
    }

    // softmax2 sums: reduce over a-lanes
#pragma unroll
    for (int o = 1; o < 8; o <<= 1) {
        part[0] += __shfl_xor_sync(0xffffffffu, part[0], o);
        part[1] += __shfl_xor_sync(0xffffffffu, part[1], o);
    }
    if (a == 0) {
        s2[4 * w + b]      = part[0];
        s2[32 + 4 * w + b] = part[1];
    }
    __syncthreads();

    const float g = gamma[0];
#pragma unroll
    for (int i = 0; i < 4; i++) {
        int n = 4 * ng + i;
        float iv = g / s2[n];
        float2 p0 = upk2(acc[i][0]), p1 = upk2(acc[i][1]);
        float vals[4] = {p0.x, p0.y, p1.x, p1.y};
#pragma unroll
        for (int cc = 0; cc < 4; cc++) {
            size_t idx = ((size_t)(d * Cn + 4 * cg + cc)) * Nn + gn0 + n;
            out[idx] = fmaf(vals[cc], iv, x[idx]);
        }
    }
}

// ============================================================================
extern "C" void kernel_launch(void* const* d_in, const int* in_sizes, int n_in,
                              void* d_out, int out_size)
{
    const float* x   = (const float*)d_in[0];
    const float* att = (const float*)d_in[1];
    const float* qw  = (const float*)d_in[2];
    const float* qb  = (const float*)d_in[3];
    const float* kw  = (const float*)d_in[4];
    const float* kb  = (const float*)d_in[5];
    const float* gm  = (const float*)d_in[6];
    float* out = (float*)d_out;

    static int smem_set = 0;
    const int dyn = (64 * 132 + 64 * 68 + 128) * 4;
    if (!smem_set) {
        cudaFuncSetAttribute(attn_v, cudaFuncAttributeMaxDynamicSharedMemorySize, dyn);
        smem_set = 1;
    }

    conv_qk    <<<dim3(Hn, Dn, 2), 256>>>(x, qw, qb, kw, kb);
    transpose_v<<<dim3(Nn / 32, Cn / 32, Dn), 256>>>(x);
    qk_scores  <<<dim3(Nn / 64, Dn), 256>>>();
    attn_v     <<<dim3(Nn / 64, Dn), 256, dyn>>>(x, att, gm, out);
}

// round 5
// speedup vs baseline: 1.4647x; 1.2789x over previous
#include <cuda_runtime.h>

#define Dn 4
#define Cn 64
#define Hn 64
#define Wn 64
#define Nn 4096
#define QKn 32
#define B1 20.0f
#define B2 8.0f
#define SPL 4
#define MCH (Nn / SPL)

typedef unsigned long long u64;

__device__ __align__(16) float g_qt[Dn * Nn * QKn];
__device__ __align__(16) float g_k [Dn * QKn * Nn];
__device__ __align__(16) float g_vt[(size_t)Dn * Nn * Cn];
__device__ __align__(16) float g_s [(size_t)Dn * Nn * Nn];
__device__ __align__(16) float g_part[(size_t)SPL * Dn * Nn * Cn];  // partial attn@V
__device__ float g_sump[SPL * Dn * Nn];   // partial softmax1 sums
__device__ float g_s2p [SPL * Dn * Nn];   // partial softmax2 sums

__device__ __forceinline__ float2 upk2(u64 v) {
    float a, b;
    asm("mov.b64 {%0,%1}, %2;" : "=f"(a), "=f"(b) : "l"(v));
    return make_float2(a, b);
}
#define FMA2(d, a, b) asm("fma.rn.f32x2 %0, %1, %2, %0;" : "+l"(d) : "l"(a), "l"(b))

// ========================= K1: conv3x3 for q,k =========================
__global__ __launch_bounds__(256) void conv_qk(
    const float* __restrict__ x,
    const float* __restrict__ qw, const float* __restrict__ qb,
    const float* __restrict__ kw, const float* __restrict__ kb)
{
    __shared__ float xs[3][16][66];
    __shared__ float wsm[16][9][32];
    const int h = blockIdx.x, d = blockIdx.y, proj = blockIdx.z;
    const int tid = threadIdx.x, oc = tid & 31, wg = tid >> 5;
    const float* wsrc = proj ? kw : qw;
    float acc[8];
    float bia = proj ? kb[oc] : qb[oc];
#pragma unroll
    for (int j = 0; j < 8; j++) acc[j] = bia;

    for (int chunk = 0; chunk < 4; chunk++) {
        for (int i = tid; i < 16 * 64; i += 256) {
            int icl = i >> 6, w = i & 63;
            const float* xp = x + ((size_t)(d * Cn + chunk * 16 + icl)) * (Hn * Wn);
#pragma unroll
            for (int dy = 0; dy < 3; dy++) {
                int hh = h + dy - 1;
                xs[dy][icl][w + 1] = (hh >= 0 && hh < Hn) ? xp[hh * Wn + w] : 0.f;
            }
            if (w == 0)
#pragma unroll
                for (int dy = 0; dy < 3; dy++) { xs[dy][icl][0] = 0.f; xs[dy][icl][65] = 0.f; }
        }
        for (int i = tid; i < 16 * 9 * 32; i += 256) {
            int icl = i / 288, rem = i % 288;
            wsm[icl][rem >> 5][rem & 31] = wsrc[((rem & 31) * Cn + chunk * 16 + icl) * 9 + (rem >> 5)];
        }
        __syncthreads();
        for (int icl = 0; icl < 16; icl++) {
#pragma unroll
            for (int dy = 0; dy < 3; dy++) {
                float xv[10];
#pragma unroll
                for (int t = 0; t < 10; t++) xv[t] = xs[dy][icl][wg * 8 + t];
#pragma unroll
                for (int dx = 0; dx < 3; dx++) {
                    float wv = wsm[icl][dy * 3 + dx][oc];
#pragma unroll
                    for (int j = 0; j < 8; j++) acc[j] = fmaf(wv, xv[dx + j], acc[j]);
                }
            }
        }
        __syncthreads();
    }
    const int n = h * Wn + wg * 8;
    if (proj == 0) {
#pragma unroll
        for (int j = 0; j < 8; j++) g_qt[((size_t)(d * Nn + n + j)) * QKn + oc] = acc[j];
    } else {
#pragma unroll
        for (int j = 0; j < 8; j++) g_k[((size_t)(d * QKn + oc)) * Nn + n + j] = acc[j];
    }
}

// ========================= K1.5: v transpose =========================
__global__ __launch_bounds__(256) void transpose_v(const float* __restrict__ x)
{
    __shared__ float t[32][33];
    const int m0 = blockIdx.x * 32, c0 = blockIdx.y * 32, d = blockIdx.z;
    const int i = threadIdx.x & 31, j = threadIdx.x >> 5;
#pragma unroll
    for (int r = 0; r < 32; r += 8)
        t[j + r][i] = x[((size_t)(d * Cn + c0 + j + r)) * Nn + m0 + i];
    __syncthreads();
#pragma unroll
    for (int r = 0; r < 32; r += 8)
        g_vt[((size_t)(d * Nn + m0 + j + r)) * Cn + c0 + i] = t[i][j + r];
}

// ========================= K2: scores + partial softmax1 sums =========================
// grid (Nn/64, Dn, SPL). block 64n x (Nn/SPL)m, thread 4n x 8m per 128-m tile.
__global__ __launch_bounds__(256) void qk_scores()
{
    __shared__ float qs[32 * 132];
    __shared__ float ks[32 * 140];

    const int d = blockIdx.y, gn0 = blockIdx.x * 64, gz = blockIdx.z;
    const int tid = threadIdx.x;
    const int mg = tid & 15, ng = tid >> 4;
    const int kcol = 8 * mg + 4 * (mg >> 2);

#pragma unroll
    for (int k = 0; k < 2; k++) {
        int i = tid + 256 * k;
        int n = i >> 3, cq = i & 7;
        float4 q4 = *(const float4*)(g_qt + ((size_t)(d * Nn + gn0 + n)) * QKn + cq * 4);
        float v[4] = {q4.x, q4.y, q4.z, q4.w};
#pragma unroll
        for (int e = 0; e < 4; e++)
            *(float2*)&qs[(cq * 4 + e) * 132 + 2 * n] = make_float2(v[e], v[e]);
    }

    float part[4] = {0.f, 0.f, 0.f, 0.f};

    for (int m0 = gz * MCH; m0 < (gz + 1) * MCH; m0 += 128) {
        __syncthreads();
#pragma unroll
        for (int k = 0; k < 4; k++) {
            int i = tid + 256 * k;
            int c = i >> 5, mq = i & 31;
            *(float4*)&ks[c * 140 + 4 * mq + 4 * (mq >> 3)] =
                *(const float4*)(g_k + ((size_t)(d * QKn + c)) * Nn + m0 + 4 * mq);
        }
        __syncthreads();

        u64 acc[4][4];
#pragma unroll
        for (int i = 0; i < 4; i++)
#pragma unroll
            for (int p = 0; p < 4; p++) acc[i][p] = 0ull;

#pragma unroll 8
        for (int c = 0; c < QKn; c++) {
            ulonglong2 qA = *(const ulonglong2*)&qs[c * 132 + 8 * ng];
            ulonglong2 qB = *(const ulonglong2*)&qs[c * 132 + 8 * ng + 4];
            ulonglong2 kA = *(const ulonglong2*)&ks[c * 140 + kcol];
            ulonglong2 kB = *(const ulonglong2*)&ks[c * 140 + kcol + 4];
            u64 q[4]  = {qA.x, qA.y, qB.x, qB.y};
            u64 kk[4] = {kA.x, kA.y, kB.x, kB.y};
#pragma unroll
            for (int i = 0; i < 4; i++) {
                FMA2(acc[i][0], q[i], kk[0]);
                FMA2(acc[i][1], q[i], kk[1]);
                FMA2(acc[i][2], q[i], kk[2]);
                FMA2(acc[i][3], q[i], kk[3]);
            }
        }

#pragma unroll
        for (int i = 0; i < 4; i++) {
            float2 p0 = upk2(acc[i][0]), p1 = upk2(acc[i][1]);
            float2 p2 = upk2(acc[i][2]), p3 = upk2(acc[i][3]);
            size_t base = ((size_t)(d * Nn + gn0 + 4 * ng + i)) * Nn + m0 + 8 * mg;
            *(float4*)(g_s + base)     = make_float4(p0.x, p0.y, p1.x, p1.y);
            *(float4*)(g_s + base + 4) = make_float4(p2.x, p2.y, p3.x, p3.y);
            part[i] += __expf(p0.x - B1) + __expf(p0.y - B1)
                     + __expf(p1.x - B1) + __expf(p1.y - B1)
                     + __expf(p2.x - B1) + __expf(p2.y - B1)
                     + __expf(p3.x - B1) + __expf(p3.y - B1);
        }
    }

#pragma unroll
    for (int o = 1; o < 16; o <<= 1)
#pragma unroll
        for (int i = 0; i < 4; i++)
            part[i] += __shfl_xor_sync(0xffffffffu, part[i], o);
    if (mg == 0)
#pragma unroll
        for (int i = 0; i < 4; i++)
            g_sump[(gz * Dn + d) * Nn + gn0 + 4 * ng + i] = part[i];
}

// ========================= K3: partial attn @ V =========================
// grid (Nn/64, Dn, SPL). block 64n x 64c over its m chunk, thread 4n x 4c.
__global__ __launch_bounds__(256) void attn_v(const float* __restrict__ atten)
{
    extern __shared__ float sh[];
    float* ts  = sh;                       // [64][132] e dup: [m][2n]
    float* vs  = sh + 64 * 132;            // [64][68]
    float* is1 = sh + 64 * 132 + 64 * 68;  // [64]

    const int d = blockIdx.y, gn0 = blockIdx.x * 64, gz = blockIdx.z;
    const int tid = threadIdx.x, lane = tid & 31, w = tid >> 5;
    const int cg = tid & 15, ng = tid >> 4;
    const int a = lane & 7, b = lane >> 3;

    if (tid < 64) {
        float s = 0.f;
#pragma unroll
        for (int p = 0; p < SPL; p++) s += g_sump[(p * Dn + d) * Nn + gn0 + tid];
        is1[tid] = 1.0f / s;
    }

    u64 acc[4][2];
#pragma unroll
    for (int i = 0; i < 4; i++) { acc[i][0] = 0ull; acc[i][1] = 0ull; }
    float part[2] = {0.f, 0.f};

    for (int m0 = gz * MCH; m0 < (gz + 1) * MCH; m0 += 64) {
        __syncthreads();
#pragma unroll
        for (int p = 0; p < 4; p++) {
#pragma unroll
            for (int q = 0; q < 2; q++) {
                int n = 32 * q + 4 * w + b;
                int ml = 16 * p + 2 * a;
                size_t base = ((size_t)(d * Nn + gn0 + n)) * Nn + m0 + ml;
                float2 sv = *(const float2*)(g_s + base);
                float2 av = *(const float2*)(atten + base);
                float ir = is1[n];
                float e0 = __expf(fmaf(__expf(sv.x - B1), ir, av.x) - B2);
                float e1 = __expf(fmaf(__expf(sv.y - B1), ir, av.y) - B2);
                part[q] += e0 + e1;
                *(float2*)&ts[ml * 132 + 2 * n]       = make_float2(e0, e0);
                *(float2*)&ts[(ml + 1) * 132 + 2 * n] = make_float2(e1, e1);
            }
        }
#pragma unroll
        for (int k = 0; k < 4; k++) {
            int m = (tid >> 4) + 16 * k;
            *(float4*)&vs[m * 68 + 4 * cg] =
                *(const float4*)(g_vt + ((size_t)(d * Nn + m0 + m)) * Cn + 4 * cg);
        }
        __syncthreads();

#pragma unroll 8
        for (int m = 0; m < 64; m++) {
            ulonglong2 eA = *(const ulonglong2*)&ts[m * 132 + 8 * ng];
            ulonglong2 vv = *(const ulonglong2*)&vs[m * 68 + 4 * cg];
            FMA2(acc[0][0], eA.x, vv.x); FMA2(acc[0][1], eA.x, vv.y);
            FMA2(acc[1][0], eA.y, vv.x); FMA2(acc[1][1], eA.y, vv.y);
            ulonglong2 eB = *(const ulonglong2*)&ts[m * 132 + 8 * ng + 4];
            FMA2(acc[2][0], eB.x, vv.x); FMA2(acc[2][1], eB.x, vv.y);
            FMA2(acc[3][0], eB.y, vv.x); FMA2(acc[3][1], eB.y, vv.y);
        }
    }

#pragma unroll
    for (int o = 1; o < 8; o <<= 1) {
        part[0] += __shfl_xor_sync(0xffffffffu, part[0], o);
        part[1] += __shfl_xor_sync(0xffffffffu, part[1], o);
    }
    if (a == 0) {
        g_s2p[(gz * Dn + d) * Nn + gn0 + 4 * w + b]      = part[0];
        g_s2p[(gz * Dn + d) * Nn + gn0 + 32 + 4 * w + b] = part[1];
    }

#pragma unroll
    for (int i = 0; i < 4; i++) {
        float2 p0 = upk2(acc[i][0]), p1 = upk2(acc[i][1]);
        *(float4*)(g_part + ((size_t)((gz * Dn + d) * Nn) + gn0 + 4 * ng + i) * Cn + 4 * cg)
            = make_float4(p0.x, p0.y, p1.x, p1.y);
    }
}

// ========================= K4: reduce partials + normalize + residual =========================
__global__ __launch_bounds__(256) void epilogue(
    const float* __restrict__ x, const float* __restrict__ gamma,
    float* __restrict__ out)
{
    __shared__ float t[32][33];
    __shared__ float inv[32];
    const int n0 = blockIdx.x * 32, c0 = blockIdx.y * 32, d = blockIdx.z;
    const int i = threadIdx.x & 31, j = threadIdx.x >> 5;
    const float g = gamma[0];

    if (threadIdx.x < 32) {
        float s = 0.f;
#pragma unroll
        for (int p = 0; p < SPL; p++) s += g_s2p[(p * Dn + d) * Nn + n0 + threadIdx.x];
        inv[threadIdx.x] = g / s;
    }
#pragma unroll
    for (int r = 0; r < 32; r += 8) {
        size_t base = ((size_t)(d * Nn) + n0 + j + r) * Cn + c0 + i;
        float v = 0.f;
#pragma unroll
        for (int p = 0; p < SPL; p++) v += g_part[(size_t)p * Dn * Nn * Cn + base];
        t[j + r][i] = v;
    }
    __syncthreads();
#pragma unroll
    for (int r = 0; r < 32; r += 8) {
        size_t idx = ((size_t)(d * Cn + c0 + j + r)) * Nn + n0 + i;
        out[idx] = fmaf(t[i][j + r], inv[i], x[idx]);
    }
}

// ============================================================================
extern "C" void kernel_launch(void* const* d_in, const int* in_sizes, int n_in,
                              void* d_out, int out_size)
{
    const float* x   = (const float*)d_in[0];
    const float* att = (const float*)d_in[1];
    const float* qw  = (const float*)d_in[2];
    const float* qb  = (const float*)d_in[3];
    const float* kw  = (const float*)d_in[4];
    const float* kb  = (const float*)d_in[5];
    const float* gm  = (const float*)d_in[6];
    float* out = (float*)d_out;

    static int smem_set = 0;
    const int dyn = (64 * 132 + 64 * 68 + 64) * 4;
    if (!smem_set) {
        cudaFuncSetAttribute(attn_v, cudaFuncAttributeMaxDynamicSharedMemorySize, dyn);
        smem_set = 1;
    }

    conv_qk    <<<dim3(Hn, Dn, 2), 256>>>(x, qw, qb, kw, kb);
    transpose_v<<<dim3(Nn / 32, Cn / 32, Dn), 256>>>(x);
    qk_scores  <<<dim3(Nn / 64, Dn, SPL), 256>>>();
    attn_v     <<<dim3(Nn / 64, Dn, SPL), 256, dyn>>>(att);
    epilogue   <<<dim3(Nn / 32, Cn / 32, Dn), 256>>>(x, gm, out);
}